// round 1
// baseline (speedup 1.0000x reference)
#include <cuda_runtime.h>
#include <math.h>

#define TT   512
#define BB   64
#define EE   256
#define UU   512
#define G4U  2048   // 4*U

// -------- device scratch (static; no allocations) --------
__device__ float g_Y[(size_t)2 * TT * G4U * BB];   // [dir][t][n][b]  512 MB
__device__ float g_h[2][2][UU][BB];                // [parity][dir][u][b]
__device__ float g_c[2][UU][BB];                   // [dir][u][b]
__device__ float g_WhT[2][G4U][UU];                // [dir][n][k]

__device__ __forceinline__ float sigm(float x) { return 1.0f / (1.0f + expf(-x)); }

// -------- zero state --------
__global__ void k_init() {
    int idx = blockIdx.x * blockDim.x + threadIdx.x;
    int n = gridDim.x * blockDim.x;
    float* h = &g_h[0][0][0][0];
    for (int i = idx; i < 2 * 2 * UU * BB; i += n) h[i] = 0.0f;
    float* c = &g_c[0][0][0];
    for (int i = idx; i < 2 * UU * BB; i += n) c[i] = 0.0f;
}

// -------- transpose Wh -> WhT[dir][n][k] --------
__global__ void k_tr(const float* __restrict__ Whf, const float* __restrict__ Whb) {
    int idx = blockIdx.x * blockDim.x + threadIdx.x;   // 2*2048*512 total
    if (idx >= 2 * G4U * UU) return;
    int dir = idx / (G4U * UU);
    int r = idx - dir * (G4U * UU);
    int nn = r / UU;
    int k  = r - nn * UU;
    const float* W = dir ? Whb : Whf;
    g_WhT[dir][nn][k] = W[(size_t)k * G4U + nn];
}

// -------- input projection: Y[dir][t][n][b] = sum_e emb[sent[b][t]][e]*Wx[e][n] + bias[n] --------
__global__ __launch_bounds__(128) void k_xw(
    const int* __restrict__ sent, const float* __restrict__ emb,
    const float* __restrict__ Wxf, const float* __restrict__ bf,
    const float* __restrict__ Wxb, const float* __restrict__ bbv)
{
    int t  = blockIdx.x;           // 0..511
    int ny = blockIdx.y;           // 0..63
    int dir = ny >> 5;
    int n0  = (ny & 31) * 64;
    const float* Wx   = dir ? Wxb : Wxf;
    const float* bias = dir ? bbv : bf;
    float* Y = g_Y + ((size_t)dir * TT + t) * (size_t)(G4U * BB);

    __shared__ float As[64 * 68];    // [e][b], stride 68 (pad: conflict-free)
    __shared__ float Bs[64 * 64];    // [e][n]
    __shared__ int   vrow[64];

    int tid = threadIdx.x;           // 128
    int tx = tid & 15, ty = tid >> 4;   // tx: b-group of 4, ty: n-group of 8

    if (tid < 64) vrow[tid] = sent[tid * TT + t];
    __syncthreads();

    float acc[4][8];
    #pragma unroll
    for (int i = 0; i < 4; i++)
        #pragma unroll
        for (int j = 0; j < 8; j++) acc[i][j] = 0.0f;

    for (int ec = 0; ec < EE; ec += 64) {
        {   // stage A (gather): thread -> (b = tid&63, half = tid>>6)
            int b = tid & 63;
            int half = tid >> 6;
            const float* er = emb + (size_t)vrow[b] * EE + ec;
            #pragma unroll
            for (int j = 0; j < 8; j++) {
                int e4 = half + 2 * j;
                float4 v = *(const float4*)(er + 4 * e4);
                int e = 4 * e4;
                As[(e + 0) * 68 + b] = v.x;
                As[(e + 1) * 68 + b] = v.y;
                As[(e + 2) * 68 + b] = v.z;
                As[(e + 3) * 68 + b] = v.w;
            }
        }
        {   // stage B
            int n4 = tid & 15, er0 = tid >> 4;
            #pragma unroll
            for (int j = 0; j < 8; j++) {
                int e = er0 + 8 * j;
                float4 v = *(const float4*)(Wx + (size_t)(ec + e) * G4U + n0 + 4 * n4);
                *(float4*)(Bs + e * 64 + 4 * n4) = v;
            }
        }
        __syncthreads();
        #pragma unroll 8
        for (int k = 0; k < 64; k++) {
            float4 a  = *(const float4*)(As + k * 68 + 4 * tx);
            float4 w0 = *(const float4*)(Bs + k * 64 + 8 * ty);
            float4 w1 = *(const float4*)(Bs + k * 64 + 8 * ty + 4);
            acc[0][0] += a.x * w0.x; acc[1][0] += a.y * w0.x; acc[2][0] += a.z * w0.x; acc[3][0] += a.w * w0.x;
            acc[0][1] += a.x * w0.y; acc[1][1] += a.y * w0.y; acc[2][1] += a.z * w0.y; acc[3][1] += a.w * w0.y;
            acc[0][2] += a.x * w0.z; acc[1][2] += a.y * w0.z; acc[2][2] += a.z * w0.z; acc[3][2] += a.w * w0.z;
            acc[0][3] += a.x * w0.w; acc[1][3] += a.y * w0.w; acc[2][3] += a.z * w0.w; acc[3][3] += a.w * w0.w;
            acc[0][4] += a.x * w1.x; acc[1][4] += a.y * w1.x; acc[2][4] += a.z * w1.x; acc[3][4] += a.w * w1.x;
            acc[0][5] += a.x * w1.y; acc[1][5] += a.y * w1.y; acc[2][5] += a.z * w1.y; acc[3][5] += a.w * w1.y;
            acc[0][6] += a.x * w1.z; acc[1][6] += a.y * w1.z; acc[2][6] += a.z * w1.z; acc[3][6] += a.w * w1.z;
            acc[0][7] += a.x * w1.w; acc[1][7] += a.y * w1.w; acc[2][7] += a.z * w1.w; acc[3][7] += a.w * w1.w;
        }
        __syncthreads();
    }
    #pragma unroll
    for (int j = 0; j < 8; j++) {
        int nn = n0 + 8 * ty + j;
        float bn = bias[nn];
        float4 o = make_float4(acc[0][j] + bn, acc[1][j] + bn, acc[2][j] + bn, acc[3][j] + bn);
        *(float4*)(Y + (size_t)nn * BB + 4 * tx) = o;
    }
}

// -------- one recurrent step (both directions), CTA owns 4 hidden units --------
__global__ __launch_bounds__(128) void k_step(int t, int p)
{
    int dir = blockIdx.x >> 7;      // 256 blocks: 128 per direction
    int ub  = blockIdx.x & 127;
    int u0  = ub * 4;
    int tid = threadIdx.x;           // 128
    int tx = tid & 15, ty = tid >> 4;   // ty 0..7 -> local cols 2ty, 2ty+1

    __shared__ float hs[64 * 64];    // [kk][b]
    __shared__ float zs[16 * 64];    // [c][b]

    const float* hin = &g_h[p][dir][0][0];

    int c0 = 2 * ty, c1 = 2 * ty + 1;
    const float* __restrict__ w0p = &g_WhT[dir][(c0 >> 2) * UU + u0 + (c0 & 3)][0];
    const float* __restrict__ w1p = &g_WhT[dir][(c1 >> 2) * UU + u0 + (c1 & 3)][0];

    float acc[8];                    // acc[bb*2 + cc]
    #pragma unroll
    for (int i = 0; i < 8; i++) acc[i] = 0.0f;

    for (int kc = 0; kc < UU; kc += 64) {
        #pragma unroll
        for (int j = 0; j < 8; j++) {
            int idx = tid + 128 * j;          // 1024 float4 copies
            ((float4*)hs)[idx] = ((const float4*)(hin + kc * 64))[idx];
        }
        __syncthreads();
        #pragma unroll
        for (int k = 0; k < 64; k += 4) {
            float4 wa = *(const float4*)(w0p + kc + k);
            float4 wb = *(const float4*)(w1p + kc + k);
            float4 h0 = *(const float4*)(hs + (k + 0) * 64 + 4 * tx);
            float4 h1 = *(const float4*)(hs + (k + 1) * 64 + 4 * tx);
            float4 h2 = *(const float4*)(hs + (k + 2) * 64 + 4 * tx);
            float4 h3 = *(const float4*)(hs + (k + 3) * 64 + 4 * tx);
            acc[0] += h0.x * wa.x; acc[2] += h0.y * wa.x; acc[4] += h0.z * wa.x; acc[6] += h0.w * wa.x;
            acc[1] += h0.x * wb.x; acc[3] += h0.y * wb.x; acc[5] += h0.z * wb.x; acc[7] += h0.w * wb.x;
            acc[0] += h1.x * wa.y; acc[2] += h1.y * wa.y; acc[4] += h1.z * wa.y; acc[6] += h1.w * wa.y;
            acc[1] += h1.x * wb.y; acc[3] += h1.y * wb.y; acc[5] += h1.z * wb.y; acc[7] += h1.w * wb.y;
            acc[0] += h2.x * wa.z; acc[2] += h2.y * wa.z; acc[4] += h2.z * wa.z; acc[6] += h2.w * wa.z;
            acc[1] += h2.x * wb.z; acc[3] += h2.y * wb.z; acc[5] += h2.z * wb.z; acc[7] += h2.w * wb.z;
            acc[0] += h3.x * wa.w; acc[2] += h3.y * wa.w; acc[4] += h3.z * wa.w; acc[6] += h3.w * wa.w;
            acc[1] += h3.x * wb.w; acc[3] += h3.y * wb.w; acc[5] += h3.z * wb.w; acc[7] += h3.w * wb.w;
        }
        __syncthreads();
    }

    #pragma unroll
    for (int i = 0; i < 4; i++) {
        zs[c0 * 64 + 4 * tx + i] = acc[i * 2 + 0];
        zs[c1 * 64 + 4 * tx + i] = acc[i * 2 + 1];
    }
    __syncthreads();

    int tt = dir ? (TT - 1 - t) : t;
    const float* Yt = g_Y + ((size_t)dir * TT + tt) * (size_t)(G4U * BB);
    float* hout = &g_h[p ^ 1][dir][0][0];
    float* cst  = &g_c[dir][0][0];

    #pragma unroll
    for (int r = 0; r < 2; r++) {
        int idx = tid + 128 * r;         // 0..255 over (du, b)
        int du = idx >> 6, b = idx & 63;
        int u = u0 + du;
        float zi = zs[(0 * 4 + du) * 64 + b] + Yt[(size_t)(0 * UU + u) * BB + b];
        float zf = zs[(1 * 4 + du) * 64 + b] + Yt[(size_t)(1 * UU + u) * BB + b];
        float zg = zs[(2 * 4 + du) * 64 + b] + Yt[(size_t)(2 * UU + u) * BB + b];
        float zo = zs[(3 * 4 + du) * 64 + b] + Yt[(size_t)(3 * UU + u) * BB + b];
        float cn = sigm(zf) * cst[u * 64 + b] + sigm(zi) * tanhf(zg);
        cst[u * 64 + b] = cn;
        hout[u * 64 + b] = sigm(zo) * tanhf(cn);
    }
}

// -------- head: out[b] = sigmoid( (h@W1+b1) @ W2 + b2 ) --------
__global__ void k_head(const float* __restrict__ W1, const float* __restrict__ b1,
                       const float* __restrict__ W2, const float* __restrict__ b2,
                       float* __restrict__ out)
{
    int b = blockIdx.x;     // 64
    int j = threadIdx.x;    // 64
    const float* hf = &g_h[0][0][0][0];
    const float* hb = &g_h[0][1][0][0];
    float s = b1[j];
    #pragma unroll 4
    for (int k = 0; k < UU; k++) s += hf[k * 64 + b] * W1[(size_t)k * 64 + j];
    #pragma unroll 4
    for (int k = 0; k < UU; k++) s += hb[k * 64 + b] * W1[(size_t)(UU + k) * 64 + j];
    float v = s * W2[j];
    __shared__ float red[64];
    red[j] = v;
    __syncthreads();
    for (int st = 32; st > 0; st >>= 1) {
        if (j < st) red[j] += red[j + st];
        __syncthreads();
    }
    if (j == 0) out[b] = sigm(red[0] + b2[0]);
}

extern "C" void kernel_launch(void* const* d_in, const int* in_sizes, int n_in,
                              void* d_out, int out_size)
{
    const int*   sent = (const int*)  d_in[0];
    const float* emb  = (const float*)d_in[1];
    const float* Wxf  = (const float*)d_in[2];
    const float* Whf  = (const float*)d_in[3];
    const float* bf   = (const float*)d_in[4];
    const float* Wxb  = (const float*)d_in[5];
    const float* Whb  = (const float*)d_in[6];
    const float* bbv  = (const float*)d_in[7];
    const float* W1   = (const float*)d_in[8];
    const float* b1   = (const float*)d_in[9];
    const float* W2   = (const float*)d_in[10];
    const float* b2   = (const float*)d_in[11];
    float* out = (float*)d_out;

    k_init<<<256, 256>>>();
    k_tr<<<(2 * G4U * UU + 255) / 256, 256>>>(Whf, Whb);
    k_xw<<<dim3(TT, 64), 128>>>(sent, emb, Wxf, bf, Wxb, bbv);
    for (int t = 0; t < TT; t++) k_step<<<256, 128>>>(t, t & 1);
    k_head<<<64, 64>>>(W1, b1, W2, b2, out);
}